// round 11
// baseline (speedup 1.0000x reference)
#include <cuda_runtime.h>

// Problem constants (match reference)
#define BB   16
#define CC   32
#define HW   384
#define NKK  32
#define HID  128
#define KOUT (NKK * 9)   // 288
#define NSLICE 8

// Conv strip geometry: each warp covers 128 cols x SR rows of one plane.
#define SR   32
#define STRIPS_PER_PLANE (3 * (HW / SR))   // 36

// Scratch (no allocations allowed in kernel_launch)
__device__ float g_part[BB * CC * NSLICE];  // partial sums per plane slice
__device__ float g_kern[BB * NKK * 9];      // [B, NK, 3, 3] generated kernels

// ---------------------------------------------------------------------------
// Kernel 1: partial average pool over a CHUNK of samples starting at b0.
// grid = (chunk*CC, NSLICE) -> 1280-1536 CTAs (stays near the 6.5TB/s rate).
// Default-cached loads leave the chunk resident in L2 for the conv pass.
// ---------------------------------------------------------------------------
__global__ void pool_kernel(const float* __restrict__ x, int b0) {
    const int bc    = b0 * CC + blockIdx.x;            // global (b,c) plane
    const int slice = blockIdx.y;
    const int n4    = HW * HW / 4 / NSLICE;            // 4608 float4 per slice
    const float4* p = (const float4*)(x + (size_t)bc * HW * HW) + slice * n4;

    float sum = 0.f;
    #pragma unroll 6
    for (int i = threadIdx.x; i < n4; i += blockDim.x) {
        float4 v = p[i];
        sum += (v.x + v.y) + (v.z + v.w);
    }

    __shared__ float red[8];
    #pragma unroll
    for (int o = 16; o; o >>= 1) sum += __shfl_xor_sync(0xffffffffu, sum, o);
    if ((threadIdx.x & 31) == 0) red[threadIdx.x >> 5] = sum;
    __syncthreads();
    if (threadIdx.x < 32) {
        float s = (threadIdx.x < (blockDim.x >> 5)) ? red[threadIdx.x] : 0.f;
        #pragma unroll
        for (int o = 4; o; o >>= 1) s += __shfl_xor_sync(0xffffffffu, s, o);
        if (threadIdx.x == 0) g_part[bc * NSLICE + slice] = s;
    }
}

// ---------------------------------------------------------------------------
// Kernel 2: reduce partials + tiny MLP for samples [b0, b0+chunk).
// ---------------------------------------------------------------------------
__global__ void mlp_kernel(const float* __restrict__ w1, const float* __restrict__ b1,
                           const float* __restrict__ w2, const float* __restrict__ b2,
                           int b0) {
    const int b = b0 + blockIdx.x;
    const int t = threadIdx.x;

    __shared__ float pooled_s[CC];
    __shared__ float hdn_s[HID];

    if (t < CC) {
        const float* pp = g_part + (b * CC + t) * NSLICE;
        float s = 0.f;
        #pragma unroll
        for (int i = 0; i < NSLICE; i++) s += pp[i];
        pooled_s[t] = s * (1.f / (float)(HW * HW));
    }
    __syncthreads();

    if (t < HID) {
        float acc = b1[t];
        #pragma unroll 8
        for (int i = 0; i < CC; i++) acc = fmaf(pooled_s[i], w1[i * HID + t], acc);
        hdn_s[t] = fmaxf(acc, 0.f);
    }
    __syncthreads();

    if (t < KOUT) {
        float acc = b2[t];
        #pragma unroll 8
        for (int i = 0; i < HID; i++) acc = fmaf(hdn_s[i], w2[i * KOUT + t], acc);
        g_kern[b * KOUT + t] = acc;
    }
}

// ---------------------------------------------------------------------------
// Kernel 3: depthwise 3x3 conv over a CHUNK of samples starting at b0.
// Direct-gmem rolling-register strips, REVERSED address order within the
// chunk (start on pool's freshest L2 lines). Reads __ldcs (last-use),
// writes __stcs (evict-first; protects the chunk's read lines in L2).
// ---------------------------------------------------------------------------
struct RowV { float l; float4 c; float r; };

__device__ __forceinline__ RowV load_row(const float* __restrict__ ip,
                                         int y, int gcol) {
    RowV v;
    if ((unsigned)y < (unsigned)HW) {
        const float* rp = ip + (size_t)y * HW + gcol;
        v.c = __ldcs((const float4*)rp);
        v.l = (gcol > 0)        ? __ldcs(rp - 1) : 0.f;
        v.r = (gcol + 4 < HW)   ? __ldcs(rp + 4) : 0.f;
    } else {
        v.c = make_float4(0.f, 0.f, 0.f, 0.f);
        v.l = 0.f; v.r = 0.f;
    }
    return v;
}

__device__ __forceinline__ void accum_row(float4& acc, const RowV& v,
                                          float w0, float w1, float w2) {
    acc.x = fmaf(w0, v.l,   fmaf(w1, v.c.x, fmaf(w2, v.c.y, acc.x)));
    acc.y = fmaf(w0, v.c.x, fmaf(w1, v.c.y, fmaf(w2, v.c.z, acc.y)));
    acc.z = fmaf(w0, v.c.y, fmaf(w1, v.c.z, fmaf(w2, v.c.w, acc.z)));
    acc.w = fmaf(w0, v.c.z, fmaf(w1, v.c.w, fmaf(w2, v.r,   acc.w)));
}

__global__ __launch_bounds__(256)
void conv_kernel(const float* __restrict__ x, float* __restrict__ out,
                 int b0, int chunk_strips) {
    const int wid_f = (blockIdx.x << 3) + (threadIdx.x >> 5);
    const int wid   = chunk_strips - 1 - wid_f;        // reversed within chunk
    const int lane  = threadIdx.x & 31;

    const int plane_l = wid / STRIPS_PER_PLANE;        // plane within chunk
    const int rem     = wid % STRIPS_PER_PLANE;        // 0..35
    const int rstrip  = rem / 3;
    const int cstrip  = rem % 3;

    const int plane = b0 * NKK + plane_l;              // global plane
    const int b  = plane >> 5;
    const int ch = plane & 31;
    const int gcol = cstrip * 128 + lane * 4;
    const int r0   = rstrip * SR;

    const float* __restrict__ ip = x   + ((size_t)b * CC + ch) * (size_t)(HW * HW);
    float*       __restrict__ op = out + (size_t)plane * (size_t)(HW * HW) + gcol;

    float w[9];
    {
        const float* kp = g_kern + plane * 9;
        #pragma unroll
        for (int i = 0; i < 9; i++) w[i] = kp[i];
    }

    RowV a  = load_row(ip, r0 - 1, gcol);
    RowV bb = load_row(ip, r0,     gcol);
    RowV c  = load_row(ip, r0 + 1, gcol);

    #pragma unroll 4
    for (int i = 0; i < SR; i++) {
        RowV d = load_row(ip, r0 + 2 + i, gcol);   // prefetch next (guarded OOB)
        float4 acc = make_float4(0.f, 0.f, 0.f, 0.f);
        accum_row(acc, a,  w[0], w[1], w[2]);
        accum_row(acc, bb, w[3], w[4], w[5]);
        accum_row(acc, c,  w[6], w[7], w[8]);
        __stcs((float4*)(op + (size_t)(r0 + i) * HW), acc);
        a = bb; bb = c; c = d;
    }
}

// ---------------------------------------------------------------------------
// Chunked schedule: {6,5,5} samples. Each chunk's input (94-113MB) fits in
// the 126MB L2, so conv(chunk) reads L2 instead of DRAM.
// ---------------------------------------------------------------------------
extern "C" void kernel_launch(void* const* d_in, const int* in_sizes, int n_in,
                              void* d_out, int out_size) {
    const float* x  = (const float*)d_in[0];
    const float* w1 = (const float*)d_in[1];
    const float* b1 = (const float*)d_in[2];
    const float* w2 = (const float*)d_in[3];
    const float* b2 = (const float*)d_in[4];
    float* out = (float*)d_out;

    const int starts[3] = {0, 6, 11};
    const int sizes_[3] = {6, 5, 5};

    for (int k = 0; k < 3; k++) {
        const int b0 = starts[k];
        const int cs = sizes_[k];
        const int strips = cs * NKK * STRIPS_PER_PLANE;    // warps in chunk

        pool_kernel<<<dim3(cs * CC, NSLICE), 256>>>(x, b0);
        mlp_kernel<<<cs, KOUT>>>(w1, b1, w2, b2, b0);
        conv_kernel<<<strips / 8, 256>>>(x, out, b0, strips);
    }
}

// round 12
// speedup vs baseline: 1.0495x; 1.0495x over previous
#include <cuda_runtime.h>

// Problem constants (match reference)
#define BB   16
#define CC   32
#define HW   384
#define NKK  32
#define HID  128
#define KOUT (NKK * 9)       // 288

// Persistent-kernel geometry
#define NCHUNK  4
#define SPLANES (BB * NKK / NCHUNK)   // 128 planes per chunk (4 samples)
#define PSLICE  4                     // pool slices per plane (512 pool CTAs)
#define SR      32                    // conv rows per strip
#define SPP     (3 * (HW / SR))       // 36 strips per plane
#define NCTA    576                   // 576*8 warps = 4608 = SPLANES*SPP exactly
#define NTHR    256

// Scratch (no allocations allowed)
__device__ float g_part[BB * CC * PSLICE];   // per-plane partial sums
__device__ int   g_bar_cnt;                  // barrier arrival counter
__device__ volatile int g_bar_gen;           // barrier generation

// ---------------------------------------------------------------------------
// Grid-wide barrier (all NCTA CTAs co-resident, guaranteed by launch bounds).
// Generation monotonically increases across replays; counter self-resets.
// ---------------------------------------------------------------------------
__device__ __forceinline__ void grid_barrier() {
    __syncthreads();
    if (threadIdx.x == 0) {
        __threadfence();                        // publish this CTA's writes
        int gen = g_bar_gen;                    // read BEFORE arriving
        if (atomicAdd(&g_bar_cnt, 1) == NCTA - 1) {
            g_bar_cnt = 0;
            __threadfence();
            g_bar_gen = gen + 1;                // release
        } else {
            while (g_bar_gen == gen) __nanosleep(64);
        }
        __threadfence();                        // acquire others' writes
    }
    __syncthreads();
}

// ---------------------------------------------------------------------------
// Conv helpers (R4/R8-proven rolling-register strip)
// ---------------------------------------------------------------------------
struct RowV { float l; float4 c; float r; };

__device__ __forceinline__ RowV load_row(const float* __restrict__ ip,
                                         int y, int gcol) {
    RowV v;
    if ((unsigned)y < (unsigned)HW) {
        const float* rp = ip + (size_t)y * HW + gcol;
        v.c = __ldcs((const float4*)rp);
        v.l = (gcol > 0)       ? __ldcs(rp - 1) : 0.f;
        v.r = (gcol + 4 < HW)  ? __ldcs(rp + 4) : 0.f;
    } else {
        v.c = make_float4(0.f, 0.f, 0.f, 0.f);
        v.l = 0.f; v.r = 0.f;
    }
    return v;
}

__device__ __forceinline__ void accum_row(float4& acc, const RowV& v,
                                          float w0, float w1, float w2) {
    acc.x = fmaf(w0, v.l,   fmaf(w1, v.c.x, fmaf(w2, v.c.y, acc.x)));
    acc.y = fmaf(w0, v.c.x, fmaf(w1, v.c.y, fmaf(w2, v.c.z, acc.y)));
    acc.z = fmaf(w0, v.c.y, fmaf(w1, v.c.z, fmaf(w2, v.c.w, acc.z)));
    acc.w = fmaf(w0, v.c.z, fmaf(w1, v.c.w, fmaf(w2, v.r,   acc.w)));
}

// ---------------------------------------------------------------------------
// The persistent kernel: for each chunk of 4 samples,
//   phase A: pool (CTAs 0..511 fill L2 with the chunk, write partials)
//   barrier
//   phase B: per-CTA redundant MLP for its sample, then conv strips
//            (reads hit the L2-resident chunk; writes stream out).
// ---------------------------------------------------------------------------
__global__ __launch_bounds__(NTHR, 4)
void fused_kernel(const float* __restrict__ x,
                  const float* __restrict__ w1, const float* __restrict__ b1,
                  const float* __restrict__ w2, const float* __restrict__ b2,
                  float* __restrict__ out) {
    const int cta  = blockIdx.x;
    const int t    = threadIdx.x;
    const int warp = t >> 5;
    const int lane = t & 31;

    __shared__ float pooled_s[CC];
    __shared__ float hdn_s[HID];
    __shared__ float kern_s[18];      // up to 2 planes per CTA
    __shared__ float red[8];

    for (int chunk = 0; chunk < NCHUNK; chunk++) {
        const int pbase = chunk * SPLANES;        // first global plane of chunk

        // ---------------- Phase A: pool ----------------
        if (cta < SPLANES * PSLICE) {             // 512 pool CTAs
            const int pl    = cta >> 2;           // local plane 0..127
            const int slice = cta & 3;
            const int gpl   = pbase + pl;         // global plane == b*CC+ch
            const int n4    = HW * HW / 4 / PSLICE;   // 9216 float4
            const float4* p = (const float4*)(x + (size_t)gpl * HW * HW) + slice * n4;

            float sum = 0.f;
            #pragma unroll 4
            for (int i = t; i < n4; i += NTHR) {
                float4 v = p[i];
                sum += (v.x + v.y) + (v.z + v.w);
            }
            #pragma unroll
            for (int o = 16; o; o >>= 1) sum += __shfl_xor_sync(0xffffffffu, sum, o);
            if (lane == 0) red[warp] = sum;
            __syncthreads();
            if (t < 32) {
                float s = (t < (NTHR >> 5)) ? red[t] : 0.f;
                #pragma unroll
                for (int o = 4; o; o >>= 1) s += __shfl_xor_sync(0xffffffffu, s, o);
                if (t == 0) g_part[gpl * PSLICE + slice] = s;
            }
        }

        grid_barrier();

        // ---------------- Phase B: MLP (redundant per CTA) + conv ----------------
        const int wid0 = cta * 8;                 // local strips wid0..wid0+7
        const int p0   = wid0 / SPP;              // first local plane of CTA
        const int p1   = (wid0 + 7) / SPP;        // last  local plane of CTA
        const int sample = (pbase + p0) >> 5;     // CTA never crosses samples

        if (t < CC) {
            const float* pp = &g_part[(sample * CC + t) * PSLICE];
            pooled_s[t] = (pp[0] + pp[1] + pp[2] + pp[3]) * (1.f / (float)(HW * HW));
        }
        __syncthreads();

        if (t < HID) {
            float acc = b1[t];
            #pragma unroll 8
            for (int i = 0; i < CC; i++) acc = fmaf(pooled_s[i], w1[i * HID + t], acc);
            hdn_s[t] = fmaxf(acc, 0.f);
        }
        __syncthreads();

        const int npl = p1 - p0 + 1;              // 1 or 2
        if (t < npl * 9) {
            const int gpl  = pbase + p0 + t / 9;
            const int cidx = (gpl & 31) * 9 + (t % 9);   // nk*9 + k
            float acc = b2[cidx];
            #pragma unroll 8
            for (int i = 0; i < HID; i++) acc = fmaf(hdn_s[i], w2[i * KOUT + cidx], acc);
            kern_s[t] = acc;
        }
        __syncthreads();

        // conv strip for this warp
        {
            const int wid   = wid0 + warp;        // local strip id
            const int pl    = wid / SPP;          // local plane
            const int rem   = wid % SPP;
            const int rstrip = rem / 3;
            const int cstrip = rem % 3;
            const int gpl   = pbase + pl;
            const int gcol  = cstrip * 128 + lane * 4;
            const int r0    = rstrip * SR;

            const float* __restrict__ ip = x   + (size_t)gpl * (size_t)(HW * HW);
            float*       __restrict__ op = out + (size_t)gpl * (size_t)(HW * HW) + gcol;

            float w[9];
            #pragma unroll
            for (int i = 0; i < 9; i++) w[i] = kern_s[(pl - p0) * 9 + i];

            RowV a  = load_row(ip, r0 - 1, gcol);
            RowV bb = load_row(ip, r0,     gcol);
            RowV c  = load_row(ip, r0 + 1, gcol);

            #pragma unroll 4
            for (int i = 0; i < SR; i++) {
                RowV d = load_row(ip, r0 + 2 + i, gcol);
                float4 acc = make_float4(0.f, 0.f, 0.f, 0.f);
                accum_row(acc, a,  w[0], w[1], w[2]);
                accum_row(acc, bb, w[3], w[4], w[5]);
                accum_row(acc, c,  w[6], w[7], w[8]);
                __stcs((float4*)(op + (size_t)(r0 + i) * HW), acc);
                a = bb; bb = c; c = d;
            }
        }
        __syncthreads();   // keep smem phases of next chunk from racing
    }
}

// ---------------------------------------------------------------------------
extern "C" void kernel_launch(void* const* d_in, const int* in_sizes, int n_in,
                              void* d_out, int out_size) {
    const float* x  = (const float*)d_in[0];
    const float* w1 = (const float*)d_in[1];
    const float* b1 = (const float*)d_in[2];
    const float* w2 = (const float*)d_in[3];
    const float* b2 = (const float*)d_in[4];
    float* out = (float*)d_out;

    fused_kernel<<<NCTA, NTHR>>>(x, w1, b1, w2, b2, out);
}

// round 13
// speedup vs baseline: 1.0764x; 1.0256x over previous
#include <cuda_runtime.h>

// Problem constants (match reference)
#define BB   16
#define CC   32
#define HW   384
#define NKK  32
#define HID  128
#define KOUT (NKK * 9)       // 288

// Persistent-kernel geometry
#define NCHUNK  4
#define SPLANES (BB * NKK / NCHUNK)   // 128 planes per chunk (4 samples)
#define PSLICE  4                     // pool slices per plane (512 pool CTAs)
#define SR      32                    // conv rows per strip
#define SPP     (3 * (HW / SR))       // 36 strips per plane
#define NCTA    576                   // 576*8 warps = 4608 = SPLANES*SPP exactly
#define NTHR    256

// Scratch (no allocations allowed)
__device__ float g_part[BB * CC * PSLICE];   // per-plane partial sums
__device__ int   g_bar_cnt;                  // barrier arrival counter
__device__ volatile int g_bar_gen;           // barrier generation

// ---------------------------------------------------------------------------
// Grid-wide barrier (all NCTA CTAs co-resident, guaranteed by launch bounds).
// Generation monotonically increases across replays; counter self-resets.
// ---------------------------------------------------------------------------
__device__ __forceinline__ void grid_barrier() {
    __syncthreads();
    if (threadIdx.x == 0) {
        __threadfence();                        // publish this CTA's writes
        int gen = g_bar_gen;                    // read BEFORE arriving
        if (atomicAdd(&g_bar_cnt, 1) == NCTA - 1) {
            g_bar_cnt = 0;
            __threadfence();
            g_bar_gen = gen + 1;                // release
        } else {
            while (g_bar_gen == gen) __nanosleep(64);
        }
        __threadfence();                        // acquire others' writes
    }
    __syncthreads();
}

// ---------------------------------------------------------------------------
// Conv helpers (R4/R8-proven rolling-register strip)
// ---------------------------------------------------------------------------
struct RowV { float l; float4 c; float r; };

__device__ __forceinline__ RowV load_row(const float* __restrict__ ip,
                                         int y, int gcol) {
    RowV v;
    if ((unsigned)y < (unsigned)HW) {
        const float* rp = ip + (size_t)y * HW + gcol;
        v.c = __ldcs((const float4*)rp);
        v.l = (gcol > 0)       ? __ldcs(rp - 1) : 0.f;
        v.r = (gcol + 4 < HW)  ? __ldcs(rp + 4) : 0.f;
    } else {
        v.c = make_float4(0.f, 0.f, 0.f, 0.f);
        v.l = 0.f; v.r = 0.f;
    }
    return v;
}

__device__ __forceinline__ void accum_row(float4& acc, const RowV& v,
                                          float w0, float w1, float w2) {
    acc.x = fmaf(w0, v.l,   fmaf(w1, v.c.x, fmaf(w2, v.c.y, acc.x)));
    acc.y = fmaf(w0, v.c.x, fmaf(w1, v.c.y, fmaf(w2, v.c.z, acc.y)));
    acc.z = fmaf(w0, v.c.y, fmaf(w1, v.c.z, fmaf(w2, v.c.w, acc.z)));
    acc.w = fmaf(w0, v.c.z, fmaf(w1, v.c.w, fmaf(w2, v.r,   acc.w)));
}

// ---------------------------------------------------------------------------
// The persistent kernel: for each chunk of 4 samples,
//   phase A: pool (CTAs 0..511 fill L2 with the chunk, write partials)
//   barrier
//   phase B: per-CTA redundant MLP for its sample, then conv strips
//            (reads hit the L2-resident chunk; writes stream out).
// ---------------------------------------------------------------------------
__global__ __launch_bounds__(NTHR, 4)
void fused_kernel(const float* __restrict__ x,
                  const float* __restrict__ w1, const float* __restrict__ b1,
                  const float* __restrict__ w2, const float* __restrict__ b2,
                  float* __restrict__ out) {
    const int cta  = blockIdx.x;
    const int t    = threadIdx.x;
    const int warp = t >> 5;
    const int lane = t & 31;

    __shared__ float pooled_s[CC];
    __shared__ float hdn_s[HID];
    __shared__ float kern_s[18];      // up to 2 planes per CTA
    __shared__ float red[8];

    for (int chunk = 0; chunk < NCHUNK; chunk++) {
        const int pbase = chunk * SPLANES;        // first global plane of chunk

        // ---------------- Phase A: pool ----------------
        if (cta < SPLANES * PSLICE) {             // 512 pool CTAs
            const int pl    = cta >> 2;           // local plane 0..127
            const int slice = cta & 3;
            const int gpl   = pbase + pl;         // global plane == b*CC+ch
            const int n4    = HW * HW / 4 / PSLICE;   // 9216 float4
            const float4* p = (const float4*)(x + (size_t)gpl * HW * HW) + slice * n4;

            float sum = 0.f;
            #pragma unroll 4
            for (int i = t; i < n4; i += NTHR) {
                float4 v = p[i];
                sum += (v.x + v.y) + (v.z + v.w);
            }
            #pragma unroll
            for (int o = 16; o; o >>= 1) sum += __shfl_xor_sync(0xffffffffu, sum, o);
            if (lane == 0) red[warp] = sum;
            __syncthreads();
            if (t < 32) {
                float s = (t < (NTHR >> 5)) ? red[t] : 0.f;
                #pragma unroll
                for (int o = 4; o; o >>= 1) s += __shfl_xor_sync(0xffffffffu, s, o);
                if (t == 0) g_part[gpl * PSLICE + slice] = s;
            }
        }

        grid_barrier();

        // ---------------- Phase B: MLP (redundant per CTA) + conv ----------------
        const int wid0 = cta * 8;                 // local strips wid0..wid0+7
        const int p0   = wid0 / SPP;              // first local plane of CTA
        const int p1   = (wid0 + 7) / SPP;        // last  local plane of CTA
        const int sample = (pbase + p0) >> 5;     // CTA never crosses samples

        if (t < CC) {
            const float* pp = &g_part[(sample * CC + t) * PSLICE];
            pooled_s[t] = (pp[0] + pp[1] + pp[2] + pp[3]) * (1.f / (float)(HW * HW));
        }
        __syncthreads();

        if (t < HID) {
            float acc = b1[t];
            #pragma unroll 8
            for (int i = 0; i < CC; i++) acc = fmaf(pooled_s[i], w1[i * HID + t], acc);
            hdn_s[t] = fmaxf(acc, 0.f);
        }
        __syncthreads();

        const int npl = p1 - p0 + 1;              // 1 or 2
        if (t < npl * 9) {
            const int gpl  = pbase + p0 + t / 9;
            const int cidx = (gpl & 31) * 9 + (t % 9);   // nk*9 + k
            float acc = b2[cidx];
            #pragma unroll 8
            for (int i = 0; i < HID; i++) acc = fmaf(hdn_s[i], w2[i * KOUT + cidx], acc);
            kern_s[t] = acc;
        }
        __syncthreads();

        // conv strip for this warp
        {
            const int wid   = wid0 + warp;        // local strip id
            const int pl    = wid / SPP;          // local plane
            const int rem   = wid % SPP;
            const int rstrip = rem / 3;
            const int cstrip = rem % 3;
            const int gpl   = pbase + pl;
            const int gcol  = cstrip * 128 + lane * 4;
            const int r0    = rstrip * SR;

            const float* __restrict__ ip = x   + (size_t)gpl * (size_t)(HW * HW);
            float*       __restrict__ op = out + (size_t)gpl * (size_t)(HW * HW) + gcol;

            float w[9];
            #pragma unroll
            for (int i = 0; i < 9; i++) w[i] = kern_s[(pl - p0) * 9 + i];

            RowV a  = load_row(ip, r0 - 1, gcol);
            RowV bb = load_row(ip, r0,     gcol);
            RowV c  = load_row(ip, r0 + 1, gcol);

            #pragma unroll 4
            for (int i = 0; i < SR; i++) {
                RowV d = load_row(ip, r0 + 2 + i, gcol);
                float4 acc = make_float4(0.f, 0.f, 0.f, 0.f);
                accum_row(acc, a,  w[0], w[1], w[2]);
                accum_row(acc, bb, w[3], w[4], w[5]);
                accum_row(acc, c,  w[6], w[7], w[8]);
                __stcs((float4*)(op + (size_t)(r0 + i) * HW), acc);
                a = bb; bb = c; c = d;
            }
        }
        __syncthreads();   // keep smem phases of next chunk from racing
    }
}

// ---------------------------------------------------------------------------
extern "C" void kernel_launch(void* const* d_in, const int* in_sizes, int n_in,
                              void* d_out, int out_size) {
    const float* x  = (const float*)d_in[0];
    const float* w1 = (const float*)d_in[1];
    const float* b1 = (const float*)d_in[2];
    const float* w2 = (const float*)d_in[3];
    const float* b2 = (const float*)d_in[4];
    float* out = (float*)d_out;

    fused_kernel<<<NCTA, NTHR>>>(x, w1, b1, w2, b2, out);
}